// round 1
// baseline (speedup 1.0000x reference)
#include <cuda_runtime.h>
#include <cuda_bf16.h>

#define D 128
#define NMAX 100000
#define EMAX 3200000

// Scratch in device globals (no allocation allowed anywhere).
__device__ float g_h0[NMAX * D];
__device__ float g_h1[NMAX * D];
__device__ float g_agg[NMAX * D];
__device__ float g_aself[NMAX];
__device__ float g_aneigh[NMAX];

// ---------------------------------------------------------------------------
// GEMM: h0 = relu(x @ W0^T + b0), h1 = relu(x @ W1^T + b1)
// Combined output [N, 256] (cols 0..127 -> h0, 128..255 -> h1).
// CTA: 256 threads, 64 rows x 256 cols tile, 8x8 accumulators per thread.
// Smem: W^T [128][257] (padded, conflict-free) + x tile [64][128].
// ---------------------------------------------------------------------------
#define WS_STRIDE 257
#define GEMM_SMEM (128 * WS_STRIDE * 4 + 64 * 128 * 4)

__global__ __launch_bounds__(256) void gemm_kernel(
    const float* __restrict__ x,
    const float* __restrict__ W0, const float* __restrict__ b0,
    const float* __restrict__ W1, const float* __restrict__ b1,
    int N)
{
    extern __shared__ float smem[];
    float* ws = smem;                      // [k][c] transposed weights, stride 257
    float* xs = smem + 128 * WS_STRIDE;    // [r][k], stride 128
    const int tid = threadIdx.x;
    const int row0 = blockIdx.x * 64;

    // Load W (both) transposed into smem. Global reads coalesced along k.
    for (int i = tid; i < 256 * 128; i += 256) {
        int c = i >> 7;        // 0..255
        int k = i & 127;
        float v = (c < 128) ? W0[c * 128 + k] : W1[(c - 128) * 128 + k];
        ws[k * WS_STRIDE + c] = v;
    }
    // Load x tile (coalesced), zero-pad out-of-range rows.
    for (int i = tid; i < 64 * 128; i += 256) {
        int r = i >> 7, k = i & 127;
        int gr = row0 + r;
        xs[i] = (gr < N) ? x[gr * 128 + k] : 0.0f;
    }
    __syncthreads();

    const int tx = tid & 31;   // col group: c = tx + j*32
    const int ty = tid >> 5;   // row group: r = ty*8 + i

    float acc[8][8];
#pragma unroll
    for (int i = 0; i < 8; i++)
#pragma unroll
        for (int j = 0; j < 8; j++) acc[i][j] = 0.0f;

#pragma unroll 4
    for (int k = 0; k < 128; k++) {
        float xv[8], wv[8];
#pragma unroll
        for (int i = 0; i < 8; i++) xv[i] = xs[(ty * 8 + i) * 128 + k];  // warp broadcast
#pragma unroll
        for (int j = 0; j < 8; j++) wv[j] = ws[k * WS_STRIDE + tx + j * 32];  // conflict-free
#pragma unroll
        for (int i = 0; i < 8; i++)
#pragma unroll
            for (int j = 0; j < 8; j++)
                acc[i][j] = fmaf(xv[i], wv[j], acc[i][j]);
    }

    // Epilogue: bias + relu, write to h0/h1 (coalesced along cols within warp).
#pragma unroll
    for (int j = 0; j < 8; j++) {
        int c = tx + j * 32;
        float bias = (c < 128) ? b0[c] : b1[c - 128];
        float* dst = (c < 128) ? g_h0 : g_h1;
        int cc = c & 127;
#pragma unroll
        for (int i = 0; i < 8; i++) {
            int gr = row0 + ty * 8 + i;
            if (gr < N) {
                float v = acc[i][j] + bias;
                dst[gr * 128 + cc] = fmaxf(v, 0.0f);
            }
        }
    }
}

// ---------------------------------------------------------------------------
// Node kernel: one warp per node.
//   a_self[i]  = leaky(h0[i] . att[0:128])
//   a_neigh[i] = leaky(h1[i] . att[128:256])
//   out[i]     = norm(h0[i], scale0, offset0)
//   agg[i]     = 0
// ---------------------------------------------------------------------------
__global__ __launch_bounds__(256) void node_kernel(
    const float* __restrict__ att,
    const float* __restrict__ scale0, const float* __restrict__ offset0,
    float* __restrict__ out, int N)
{
    int gw = (blockIdx.x * blockDim.x + threadIdx.x) >> 5;
    int lane = threadIdx.x & 31;
    if (gw >= N) return;

    const float4 a = ((const float4*)(g_h0 + (size_t)gw * 128))[lane];
    const float4 b = ((const float4*)(g_h1 + (size_t)gw * 128))[lane];
    const float4 at0 = ((const float4*)att)[lane];
    const float4 at1 = ((const float4*)att)[32 + lane];

    float s  = a.x + a.y + a.z + a.w;
    float ss = a.x * a.x + a.y * a.y + a.z * a.z + a.w * a.w;
    float d0 = a.x * at0.x + a.y * at0.y + a.z * at0.z + a.w * at0.w;
    float d1 = b.x * at1.x + b.y * at1.y + b.z * at1.z + b.w * at1.w;

#pragma unroll
    for (int o = 16; o > 0; o >>= 1) {
        s  += __shfl_xor_sync(0xffffffffu, s,  o);
        ss += __shfl_xor_sync(0xffffffffu, ss, o);
        d0 += __shfl_xor_sync(0xffffffffu, d0, o);
        d1 += __shfl_xor_sync(0xffffffffu, d1, o);
    }

    const float m   = s * (1.0f / 128.0f);
    const float var = ss * (1.0f / 128.0f) - m * m;
    const float inv = rsqrtf(var + 1e-9f);

    const float4 sc = ((const float4*)scale0)[lane];
    const float4 of = ((const float4*)offset0)[lane];
    float4 o4;
    o4.x = (a.x - m) * sc.x * inv + of.x;
    o4.y = (a.y - m) * sc.y * inv + of.y;
    o4.z = (a.z - m) * sc.z * inv + of.z;
    o4.w = (a.w - m) * sc.w * inv + of.w;
    ((float4*)(out + (size_t)gw * 128))[lane] = o4;

    if (lane == 0) {
        g_aself[gw]  = (d0 > 0.0f) ? d0 : 0.2f * d0;
        g_aneigh[gw] = (d1 > 0.0f) ? d1 : 0.2f * d1;
    }
    ((float4*)(g_agg + (size_t)gw * 128))[lane] = make_float4(0.f, 0.f, 0.f, 0.f);
}

// ---------------------------------------------------------------------------
// Edge kernel: one warp per edge.
//   agg[row] += (a_self[row] + a_neigh[col]) * h1[col]
// using red.global.add.v4.f32 (sm_90+ vector float reduction, no return).
// ---------------------------------------------------------------------------
__global__ __launch_bounds__(256) void edge_kernel(
    const int* __restrict__ row, const int* __restrict__ col, int E)
{
    int gw = (blockIdx.x * blockDim.x + threadIdx.x) >> 5;
    int lane = threadIdx.x & 31;
    if (gw >= E) return;

    // All lanes load the same address -> single-sector broadcast loads.
    const int r = __ldg(row + gw);
    const int c = __ldg(col + gw);
    const float e = g_aself[r] + g_aneigh[c];

    const float4 h = ((const float4*)(g_h1 + (size_t)c * 128))[lane];
    float* dst = g_agg + (size_t)r * 128 + lane * 4;
    asm volatile(
        "red.global.add.v4.f32 [%0], {%1, %2, %3, %4};"
        :: "l"(dst), "f"(e * h.x), "f"(e * h.y), "f"(e * h.z), "f"(e * h.w)
        : "memory");
}

// ---------------------------------------------------------------------------
// Final kernel: one warp per node.  out[i] += norm(agg[i], scale1, offset1)
// ---------------------------------------------------------------------------
__global__ __launch_bounds__(256) void final_kernel(
    const float* __restrict__ scale1, const float* __restrict__ offset1,
    float* __restrict__ out, int N)
{
    int gw = (blockIdx.x * blockDim.x + threadIdx.x) >> 5;
    int lane = threadIdx.x & 31;
    if (gw >= N) return;

    const float4 a = ((const float4*)(g_agg + (size_t)gw * 128))[lane];

    float s  = a.x + a.y + a.z + a.w;
    float ss = a.x * a.x + a.y * a.y + a.z * a.z + a.w * a.w;
#pragma unroll
    for (int o = 16; o > 0; o >>= 1) {
        s  += __shfl_xor_sync(0xffffffffu, s,  o);
        ss += __shfl_xor_sync(0xffffffffu, ss, o);
    }
    const float m   = s * (1.0f / 128.0f);
    const float var = ss * (1.0f / 128.0f) - m * m;
    const float inv = rsqrtf(var + 1e-9f);

    const float4 sc = ((const float4*)scale1)[lane];
    const float4 of = ((const float4*)offset1)[lane];

    float4* op = (float4*)(out + (size_t)gw * 128) + lane;
    float4 o4 = *op;
    o4.x += (a.x - m) * sc.x * inv + of.x;
    o4.y += (a.y - m) * sc.y * inv + of.y;
    o4.z += (a.z - m) * sc.z * inv + of.z;
    o4.w += (a.w - m) * sc.w * inv + of.w;
    *op = o4;
}

// ---------------------------------------------------------------------------
extern "C" void kernel_launch(void* const* d_in, const int* in_sizes, int n_in,
                              void* d_out, int out_size)
{
    const float* x       = (const float*)d_in[0];
    const int*   row     = (const int*)  d_in[1];
    const int*   col     = (const int*)  d_in[2];
    const float* W0      = (const float*)d_in[3];
    const float* b0      = (const float*)d_in[4];
    const float* W1      = (const float*)d_in[5];
    const float* b1      = (const float*)d_in[6];
    const float* att     = (const float*)d_in[7];
    const float* scale0  = (const float*)d_in[8];
    const float* offset0 = (const float*)d_in[9];
    const float* scale1  = (const float*)d_in[10];
    const float* offset1 = (const float*)d_in[11];
    float* out = (float*)d_out;

    const int N = in_sizes[0] / D;
    const int E = in_sizes[1];

    cudaFuncSetAttribute(gemm_kernel, cudaFuncAttributeMaxDynamicSharedMemorySize,
                         GEMM_SMEM);

    gemm_kernel<<<(N + 63) / 64, 256, GEMM_SMEM>>>(x, W0, b0, W1, b1, N);
    node_kernel<<<(N * 32 + 255) / 256, 256>>>(att, scale0, offset0, out, N);
    {
        long long threads = (long long)E * 32;
        int blocks = (int)((threads + 255) / 256);
        edge_kernel<<<blocks, 256>>>(row, col, E);
    }
    final_kernel<<<(N * 32 + 255) / 256, 256>>>(scale1, offset1, out, N);
}

// round 3
// speedup vs baseline: 1.5174x; 1.5174x over previous
#include <cuda_runtime.h>
#include <cuda_bf16.h>

#define D 128
#define NMAX 100000
#define EMAX 3200000
#define FULL 0xffffffffu

// Scratch in device globals (module-load allocations; legal).
__device__ float g_h0[NMAX * D];
__device__ float g_h1[NMAX * D];
__device__ float g_aself[NMAX];
__device__ float g_aneigh[NMAX];
__device__ int   g_deg[NMAX];
__device__ int   g_off[NMAX + 1];
__device__ int   g_cur[NMAX];
__device__ int   g_ecol[EMAX];
__device__ int   g_bsum[512];
__device__ int   g_boff[512];

// ---------------------------------------------------------------------------
// GEMM: h0 = relu(x@W0^T+b0), h1 = relu(x@W1^T+b1), fused attention dots:
//   a_self[r]  = leaky(h0[r] . att[0:128])
//   a_neigh[r] = leaky(h1[r] . att[128:256])
// Also zeroes g_deg (each row covered exactly once across the grid).
// CTA: 256 thr, 64 rows x 256 cols, 8x8 per-thread accumulators.
// ---------------------------------------------------------------------------
#define WS_STRIDE 257
#define GEMM_SMEM (128 * WS_STRIDE * 4 + 64 * 128 * 4)

__global__ __launch_bounds__(256) void gemm_kernel(
    const float* __restrict__ x,
    const float* __restrict__ W0, const float* __restrict__ b0,
    const float* __restrict__ W1, const float* __restrict__ b1,
    const float* __restrict__ att, int N)
{
    extern __shared__ float smem[];
    float* ws = smem;                      // [k][c] transposed weights, stride 257
    float* xs = smem + 128 * WS_STRIDE;    // [r][k]
    const int tid = threadIdx.x;
    const int row0 = blockIdx.x * 64;

    if (tid < 64 && row0 + tid < N) g_deg[row0 + tid] = 0;

    for (int i = tid; i < 256 * 128; i += 256) {
        int c = i >> 7, k = i & 127;
        float v = (c < 128) ? W0[c * 128 + k] : W1[(c - 128) * 128 + k];
        ws[k * WS_STRIDE + c] = v;
    }
    for (int i = tid; i < 64 * 128; i += 256) {
        int r = i >> 7, k = i & 127;
        int gr = row0 + r;
        xs[i] = (gr < N) ? x[gr * 128 + k] : 0.0f;
    }
    __syncthreads();

    const int tx = tid & 31;   // lane: col = tx + j*32
    const int ty = tid >> 5;   // warp: rows ty*8 + i

    float acc[8][8];
#pragma unroll
    for (int i = 0; i < 8; i++)
#pragma unroll
        for (int j = 0; j < 8; j++) acc[i][j] = 0.0f;

#pragma unroll 4
    for (int k = 0; k < 128; k++) {
        float xv[8], wv[8];
#pragma unroll
        for (int i = 0; i < 8; i++) xv[i] = xs[(ty * 8 + i) * 128 + k];
#pragma unroll
        for (int j = 0; j < 8; j++) wv[j] = ws[k * WS_STRIDE + tx + j * 32];
#pragma unroll
        for (int i = 0; i < 8; i++)
#pragma unroll
            for (int j = 0; j < 8; j++)
                acc[i][j] = fmaf(xv[i], wv[j], acc[i][j]);
    }

    // Epilogue: bias + relu, store h0/h1, fused attention dots.
    float attv[8], bias[8];
#pragma unroll
    for (int j = 0; j < 8; j++) {
        int c = tx + j * 32;
        attv[j] = att[c];
        bias[j] = (c < 128) ? b0[c] : b1[c - 128];
    }

#pragma unroll
    for (int i = 0; i < 8; i++) {
        int gr = row0 + ty * 8 + i;
        float p0 = 0.0f, p1 = 0.0f;
#pragma unroll
        for (int j = 0; j < 8; j++) {
            int c = tx + j * 32;
            float v = fmaxf(acc[i][j] + bias[j], 0.0f);
            if (gr < N) {
                float* dst = (c < 128) ? g_h0 : g_h1;
                dst[(size_t)gr * 128 + (c & 127)] = v;
            }
            if (c < 128) p0 = fmaf(v, attv[j], p0);
            else         p1 = fmaf(v, attv[j], p1);
        }
#pragma unroll
        for (int o = 16; o > 0; o >>= 1) {
            p0 += __shfl_xor_sync(FULL, p0, o);
            p1 += __shfl_xor_sync(FULL, p1, o);
        }
        if (tx == 0 && gr < N) {
            g_aself[gr]  = (p0 > 0.0f) ? p0 : 0.2f * p0;
            g_aneigh[gr] = (p1 > 0.0f) ? p1 : 0.2f * p1;
        }
    }
}

// ---------------------------------------------------------------------------
// CSR build: histogram -> 3-kernel scan -> cursor scatter
// ---------------------------------------------------------------------------
__global__ __launch_bounds__(256) void hist_kernel(const int* __restrict__ row, int E)
{
    int i = blockIdx.x * 256 + threadIdx.x;
    if (i < E) atomicAdd(&g_deg[row[i]], 1);
}

__global__ __launch_bounds__(512) void scan1_kernel(int N)
{
    int t = threadIdx.x, b = blockIdx.x;
    int i = b * 512 + t;
    int lane = t & 31, w = t >> 5;
    int v = (i < N) ? g_deg[i] : 0;
#pragma unroll
    for (int o = 1; o < 32; o <<= 1) {
        int n = __shfl_up_sync(FULL, v, o);
        if (lane >= o) v += n;
    }
    __shared__ int ws[16];
    if (lane == 31) ws[w] = v;
    __syncthreads();
    if (w == 0) {
        int s = (lane < 16) ? ws[lane] : 0;
#pragma unroll
        for (int o = 1; o < 16; o <<= 1) {
            int n = __shfl_up_sync(FULL, s, o);
            if (lane >= o) s += n;
        }
        if (lane < 16) ws[lane] = s;
    }
    __syncthreads();
    if (w > 0) v += ws[w - 1];
    if (i < N) g_off[i + 1] = v;
    if (t == 511) g_bsum[b] = v;
}

__global__ __launch_bounds__(512) void scan2_kernel(int nb)
{
    int t = threadIdx.x;
    int lane = t & 31, w = t >> 5;
    int orig = (t < nb) ? g_bsum[t] : 0;
    int v = orig;
#pragma unroll
    for (int o = 1; o < 32; o <<= 1) {
        int n = __shfl_up_sync(FULL, v, o);
        if (lane >= o) v += n;
    }
    __shared__ int ws[16];
    if (lane == 31) ws[w] = v;
    __syncthreads();
    if (w == 0) {
        int s = (lane < 16) ? ws[lane] : 0;
#pragma unroll
        for (int o = 1; o < 16; o <<= 1) {
            int n = __shfl_up_sync(FULL, s, o);
            if (lane >= o) s += n;
        }
        if (lane < 16) ws[lane] = s;
    }
    __syncthreads();
    if (w > 0) v += ws[w - 1];
    if (t < nb) g_boff[t] = v - orig;   // exclusive
}

__global__ __launch_bounds__(512) void scan3_kernel(int N)
{
    int t = threadIdx.x, b = blockIdx.x;
    int i = b * 512 + t;
    if (i < N) {
        int val = g_off[i + 1] + g_boff[b];
        g_off[i + 1] = val;
        g_cur[i] = val - g_deg[i];
    }
    if (i == 0) g_off[0] = 0;
}

__global__ __launch_bounds__(256) void scatter_kernel(
    const int* __restrict__ row, const int* __restrict__ col, int E)
{
    int i = blockIdx.x * 256 + threadIdx.x;
    if (i < E) {
        int pos = atomicAdd(&g_cur[row[i]], 1);
        g_ecol[pos] = col[i];
    }
}

// ---------------------------------------------------------------------------
// Aggregate + fused epilogue: one warp per node.
//   agg = sum_{edges(r,c)} (a_self[r]+a_neigh[c]) * h1[c]   (registers, no atomics)
//   out[r] = norm(h0[r],s0,o0) + norm(agg,s1,o1)
// ---------------------------------------------------------------------------
__global__ __launch_bounds__(256) void agg_kernel(
    const float* __restrict__ scale0, const float* __restrict__ offset0,
    const float* __restrict__ scale1, const float* __restrict__ offset1,
    float* __restrict__ out, int N)
{
    int gw = (blockIdx.x * blockDim.x + threadIdx.x) >> 5;
    int lane = threadIdx.x & 31;
    if (gw >= N) return;

    const int start = g_off[gw];
    const int end   = g_off[gw + 1];
    const float a_r = g_aself[gw];

    float4 acc = make_float4(0.f, 0.f, 0.f, 0.f);

    for (int base = start; base < end; base += 32) {
        int idx = base + lane;
        int c = (idx < end) ? g_ecol[idx] : 0;
        float e = (idx < end) ? a_r + g_aneigh[c] : 0.0f;
        int cnt = min(32, end - base);
        int j = 0;
        for (; j + 4 <= cnt; j += 4) {
#pragma unroll
            for (int u = 0; u < 4; u++) {
                int   cj = __shfl_sync(FULL, c, j + u);
                float ej = __shfl_sync(FULL, e, j + u);
                const float4 h = ((const float4*)(g_h1 + (size_t)cj * 128))[lane];
                acc.x = fmaf(ej, h.x, acc.x);
                acc.y = fmaf(ej, h.y, acc.y);
                acc.z = fmaf(ej, h.z, acc.z);
                acc.w = fmaf(ej, h.w, acc.w);
            }
        }
        for (; j < cnt; j++) {
            int   cj = __shfl_sync(FULL, c, j);
            float ej = __shfl_sync(FULL, e, j);
            const float4 h = ((const float4*)(g_h1 + (size_t)cj * 128))[lane];
            acc.x = fmaf(ej, h.x, acc.x);
            acc.y = fmaf(ej, h.y, acc.y);
            acc.z = fmaf(ej, h.z, acc.z);
            acc.w = fmaf(ej, h.w, acc.w);
        }
    }

    const float4 h0v = ((const float4*)(g_h0 + (size_t)gw * 128))[lane];

    float s0 = h0v.x + h0v.y + h0v.z + h0v.w;
    float q0 = h0v.x * h0v.x + h0v.y * h0v.y + h0v.z * h0v.z + h0v.w * h0v.w;
    float s1 = acc.x + acc.y + acc.z + acc.w;
    float q1 = acc.x * acc.x + acc.y * acc.y + acc.z * acc.z + acc.w * acc.w;

#pragma unroll
    for (int o = 16; o > 0; o >>= 1) {
        s0 += __shfl_xor_sync(FULL, s0, o);
        q0 += __shfl_xor_sync(FULL, q0, o);
        s1 += __shfl_xor_sync(FULL, s1, o);
        q1 += __shfl_xor_sync(FULL, q1, o);
    }

    const float m0 = s0 * (1.0f / 128.0f);
    const float i0 = rsqrtf(q0 * (1.0f / 128.0f) - m0 * m0 + 1e-9f);
    const float m1 = s1 * (1.0f / 128.0f);
    const float i1 = rsqrtf(q1 * (1.0f / 128.0f) - m1 * m1 + 1e-9f);

    const float4 sc0 = ((const float4*)scale0)[lane];
    const float4 of0 = ((const float4*)offset0)[lane];
    const float4 sc1 = ((const float4*)scale1)[lane];
    const float4 of1 = ((const float4*)offset1)[lane];

    float4 o4;
    o4.x = (h0v.x - m0) * sc0.x * i0 + of0.x + (acc.x - m1) * sc1.x * i1 + of1.x;
    o4.y = (h0v.y - m0) * sc0.y * i0 + of0.y + (acc.y - m1) * sc1.y * i1 + of1.y;
    o4.z = (h0v.z - m0) * sc0.z * i0 + of0.z + (acc.z - m1) * sc1.z * i1 + of1.z;
    o4.w = (h0v.w - m0) * sc0.w * i0 + of0.w + (acc.w - m1) * sc1.w * i1 + of1.w;
    ((float4*)(out + (size_t)gw * 128))[lane] = o4;
}

// ---------------------------------------------------------------------------
extern "C" void kernel_launch(void* const* d_in, const int* in_sizes, int n_in,
                              void* d_out, int out_size)
{
    const float* x       = (const float*)d_in[0];
    const int*   row     = (const int*)  d_in[1];
    const int*   col     = (const int*)  d_in[2];
    const float* W0      = (const float*)d_in[3];
    const float* b0      = (const float*)d_in[4];
    const float* W1      = (const float*)d_in[5];
    const float* b1      = (const float*)d_in[6];
    const float* att     = (const float*)d_in[7];
    const float* scale0  = (const float*)d_in[8];
    const float* offset0 = (const float*)d_in[9];
    const float* scale1  = (const float*)d_in[10];
    const float* offset1 = (const float*)d_in[11];
    float* out = (float*)d_out;

    const int N = in_sizes[0] / D;
    const int E = in_sizes[1];
    const int nb = (N + 511) / 512;      // scan blocks (<=512 supported)

    cudaFuncSetAttribute(gemm_kernel, cudaFuncAttributeMaxDynamicSharedMemorySize,
                         GEMM_SMEM);

    gemm_kernel<<<(N + 63) / 64, 256, GEMM_SMEM>>>(x, W0, b0, W1, b1, att, N);
    hist_kernel<<<(E + 255) / 256, 256>>>(row, E);
    scan1_kernel<<<nb, 512>>>(N);
    scan2_kernel<<<1, 512>>>(nb);
    scan3_kernel<<<nb, 512>>>(N);
    scatter_kernel<<<(E + 255) / 256, 256>>>(row, col, E);
    agg_kernel<<<(N * 32 + 255) / 256, 256>>>(scale0, offset0, scale1, offset1, out, N);
}

// round 4
// speedup vs baseline: 2.1665x; 1.4277x over previous
#include <cuda_runtime.h>
#include <cstdint>

#define D 128
#define NMAX 100000
#define EMAX 3200000
#define FULL 0xffffffffu

// Scratch in device globals (no runtime allocation).
__device__ float g_h0[NMAX * D];
__device__ float g_h1[NMAX * D];
__device__ float g_aself[NMAX];
__device__ float g_aneigh[NMAX];
__device__ int   g_deg[NMAX];
__device__ int   g_off[NMAX + 1];
__device__ int   g_cur[NMAX];
__device__ int   g_ecol[EMAX];
__device__ int   g_bsum[512];
__device__ int   g_boff[512];

// ---------------------------------------------------------------------------
// Tensor-core GEMM (tf32 mma.sync m16n8k8).
// Grid (ceil(N/128), 2): blockIdx.y = cb selects (W0,b0,att[0:128]) -> h0/a_self
//                                  or (W1,b1,att[128:256]) -> h1/a_neigh.
// CTA: 256 thr (8 warps, 4x2), tile 128 rows x 128 cols.
// smem tiles hold tf32-converted bits, stride 132 words (bank = lane, no conflicts).
// ---------------------------------------------------------------------------
#define TSTRIDE 132
#define TILE_WORDS (128 * TSTRIDE)
#define GEMM_SMEM ((2 * TILE_WORDS + 3 * 128) * 4)

__device__ __forceinline__ uint32_t f2tf32(float f)
{
    uint32_t u;
    asm("cvt.rna.tf32.f32 %0, %1;" : "=r"(u) : "f"(f));
    return u;
}

__device__ __forceinline__ void mma_tf32(float* c, const uint32_t* a,
                                         uint32_t b0, uint32_t b1)
{
    asm volatile(
        "mma.sync.aligned.m16n8k8.row.col.f32.tf32.tf32.f32 "
        "{%0,%1,%2,%3}, {%4,%5,%6,%7}, {%8,%9}, {%0,%1,%2,%3};"
        : "+f"(c[0]), "+f"(c[1]), "+f"(c[2]), "+f"(c[3])
        : "r"(a[0]), "r"(a[1]), "r"(a[2]), "r"(a[3]), "r"(b0), "r"(b1));
}

__global__ __launch_bounds__(256) void gemm_kernel(
    const float* __restrict__ x,
    const float* __restrict__ W0, const float* __restrict__ b0,
    const float* __restrict__ W1, const float* __restrict__ b1,
    const float* __restrict__ att, int N)
{
    extern __shared__ uint32_t sm[];
    uint32_t* xs = sm;                    // [r][k] tf32 bits, stride 132
    uint32_t* ws = sm + TILE_WORDS;       // [n][k] tf32 bits, stride 132
    float* rowsum = (float*)(sm + 2 * TILE_WORDS);
    float* sbias  = rowsum + 128;
    float* satt   = sbias + 128;

    const int tid  = threadIdx.x;
    const int row0 = blockIdx.x * 128;
    const int cb   = blockIdx.y;
    const float* W  = cb ? W1 : W0;
    const float* bv = cb ? b1 : b0;

    if (tid < 128) {
        rowsum[tid] = 0.0f;
        sbias[tid]  = bv[tid];
        satt[tid]   = att[cb * 128 + tid];
        if (cb == 0 && row0 + tid < N) g_deg[row0 + tid] = 0;
    }

    // Stage tiles (x zero-padded past N; W tile = full 128x128 weight matrix).
    for (int i = tid; i < 128 * 128; i += 256) {
        int r = i >> 7, c = i & 127;
        int gr = row0 + r;
        float xv = (gr < N) ? x[(size_t)gr * 128 + c] : 0.0f;
        xs[r * TSTRIDE + c] = f2tf32(xv);
        ws[r * TSTRIDE + c] = f2tf32(W[r * 128 + c]);
    }
    __syncthreads();

    const int lane = tid & 31, wid = tid >> 5;
    const int gid  = lane >> 2, tg = lane & 3;
    const int mrow = (wid >> 1) * 32;   // 0,32,64,96
    const int ncol = (wid & 1) * 64;    // 0,64

    float acc[2][8][4];
#pragma unroll
    for (int mt = 0; mt < 2; mt++)
#pragma unroll
        for (int nt = 0; nt < 8; nt++)
#pragma unroll
            for (int q = 0; q < 4; q++) acc[mt][nt][q] = 0.0f;

#pragma unroll 2
    for (int ks = 0; ks < 16; ks++) {
        const int k0 = ks * 8;
        uint32_t a[2][4];
#pragma unroll
        for (int mt = 0; mt < 2; mt++) {
            int r = mrow + mt * 16 + gid;
            a[mt][0] = xs[(r    ) * TSTRIDE + k0 + tg    ];
            a[mt][1] = xs[(r + 8) * TSTRIDE + k0 + tg    ];
            a[mt][2] = xs[(r    ) * TSTRIDE + k0 + tg + 4];
            a[mt][3] = xs[(r + 8) * TSTRIDE + k0 + tg + 4];
        }
#pragma unroll
        for (int nt = 0; nt < 8; nt++) {
            int n = ncol + nt * 8 + gid;
            uint32_t bq0 = ws[n * TSTRIDE + k0 + tg    ];
            uint32_t bq1 = ws[n * TSTRIDE + k0 + tg + 4];
#pragma unroll
            for (int mt = 0; mt < 2; mt++)
                mma_tf32(acc[mt][nt], a[mt], bq0, bq1);
        }
    }

    // Epilogue: bias + relu, store h, accumulate attention dot per row.
    float* dst = cb ? g_h1 : g_h0;
    float pr[2][2] = {{0.f, 0.f}, {0.f, 0.f}};
#pragma unroll
    for (int mt = 0; mt < 2; mt++) {
        int rbase = row0 + mrow + mt * 16;
#pragma unroll
        for (int nt = 0; nt < 8; nt++) {
            int n = ncol + nt * 8 + 2 * tg;
            float bia0 = sbias[n], bia1 = sbias[n + 1];
            float at0  = satt[n],  at1  = satt[n + 1];
            float v00 = fmaxf(acc[mt][nt][0] + bia0, 0.0f);
            float v01 = fmaxf(acc[mt][nt][1] + bia1, 0.0f);
            float v10 = fmaxf(acc[mt][nt][2] + bia0, 0.0f);
            float v11 = fmaxf(acc[mt][nt][3] + bia1, 0.0f);
            int r0r = rbase + gid, r1r = rbase + gid + 8;
            if (r0r < N) *(float2*)(dst + (size_t)r0r * 128 + n) = make_float2(v00, v01);
            if (r1r < N) *(float2*)(dst + (size_t)r1r * 128 + n) = make_float2(v10, v11);
            pr[mt][0] += v00 * at0 + v01 * at1;
            pr[mt][1] += v10 * at0 + v11 * at1;
        }
    }
    // Reduce over the quad (tg) then combine warps via smem atomics.
#pragma unroll
    for (int mt = 0; mt < 2; mt++)
#pragma unroll
        for (int h = 0; h < 2; h++) {
            float p = pr[mt][h];
            p += __shfl_xor_sync(FULL, p, 1);
            p += __shfl_xor_sync(FULL, p, 2);
            pr[mt][h] = p;
        }
    if (tg == 0) {
        atomicAdd(&rowsum[mrow + gid     ], pr[0][0]);
        atomicAdd(&rowsum[mrow + gid + 8 ], pr[0][1]);
        atomicAdd(&rowsum[mrow + gid + 16], pr[1][0]);
        atomicAdd(&rowsum[mrow + gid + 24], pr[1][1]);
    }
    __syncthreads();
    if (tid < 128) {
        int gr = row0 + tid;
        if (gr < N) {
            float p = rowsum[tid];
            p = (p > 0.0f) ? p : 0.2f * p;
            if (cb) g_aneigh[gr] = p;
            else    g_aself[gr]  = p;
        }
    }
}

// ---------------------------------------------------------------------------
// CSR build: histogram -> 3-kernel scan -> cursor scatter
// ---------------------------------------------------------------------------
__global__ __launch_bounds__(256) void hist_kernel(const int* __restrict__ row, int E)
{
    int i = blockIdx.x * 256 + threadIdx.x;
    if (i < E) atomicAdd(&g_deg[row[i]], 1);
}

__global__ __launch_bounds__(512) void scan1_kernel(int N)
{
    int t = threadIdx.x, b = blockIdx.x;
    int i = b * 512 + t;
    int lane = t & 31, w = t >> 5;
    int v = (i < N) ? g_deg[i] : 0;
#pragma unroll
    for (int o = 1; o < 32; o <<= 1) {
        int n = __shfl_up_sync(FULL, v, o);
        if (lane >= o) v += n;
    }
    __shared__ int ws[16];
    if (lane == 31) ws[w] = v;
    __syncthreads();
    if (w == 0) {
        int s = (lane < 16) ? ws[lane] : 0;
#pragma unroll
        for (int o = 1; o < 16; o <<= 1) {
            int n = __shfl_up_sync(FULL, s, o);
            if (lane >= o) s += n;
        }
        if (lane < 16) ws[lane] = s;
    }
    __syncthreads();
    if (w > 0) v += ws[w - 1];
    if (i < N) g_off[i + 1] = v;
    if (t == 511) g_bsum[b] = v;
}

__global__ __launch_bounds__(512) void scan2_kernel(int nb)
{
    int t = threadIdx.x;
    int lane = t & 31, w = t >> 5;
    int orig = (t < nb) ? g_bsum[t] : 0;
    int v = orig;
#pragma unroll
    for (int o = 1; o < 32; o <<= 1) {
        int n = __shfl_up_sync(FULL, v, o);
        if (lane >= o) v += n;
    }
    __shared__ int ws[16];
    if (lane == 31) ws[w] = v;
    __syncthreads();
    if (w == 0) {
        int s = (lane < 16) ? ws[lane] : 0;
#pragma unroll
        for (int o = 1; o < 16; o <<= 1) {
            int n = __shfl_up_sync(FULL, s, o);
            if (lane >= o) s += n;
        }
        if (lane < 16) ws[lane] = s;
    }
    __syncthreads();
    if (w > 0) v += ws[w - 1];
    if (t < nb) g_boff[t] = v - orig;   // exclusive
}

__global__ __launch_bounds__(512) void scan3_kernel(int N)
{
    int t = threadIdx.x, b = blockIdx.x;
    int i = b * 512 + t;
    if (i < N) {
        int val = g_off[i + 1] + g_boff[b];
        g_off[i + 1] = val;
        g_cur[i] = val - g_deg[i];
    }
    if (i == 0) g_off[0] = 0;
}

__global__ __launch_bounds__(256) void scatter_kernel(
    const int* __restrict__ row, const int* __restrict__ col, int E)
{
    int i = blockIdx.x * 256 + threadIdx.x;
    if (i < E) {
        int pos = atomicAdd(&g_cur[row[i]], 1);
        g_ecol[pos] = col[i];
    }
}

// ---------------------------------------------------------------------------
// Aggregate + fused epilogue: one warp per node (gather, no atomics).
//   agg = sum_{(r,c)} (a_self[r]+a_neigh[c]) * h1[c]
//   out[r] = norm(h0[r],s0,o0) + norm(agg,s1,o1)
// ---------------------------------------------------------------------------
__global__ __launch_bounds__(256) void agg_kernel(
    const float* __restrict__ scale0, const float* __restrict__ offset0,
    const float* __restrict__ scale1, const float* __restrict__ offset1,
    float* __restrict__ out, int N)
{
    int gw = (blockIdx.x * blockDim.x + threadIdx.x) >> 5;
    int lane = threadIdx.x & 31;
    if (gw >= N) return;

    const int start = g_off[gw];
    const int end   = g_off[gw + 1];
    const float a_r = g_aself[gw];

    float4 acc = make_float4(0.f, 0.f, 0.f, 0.f);

    for (int base = start; base < end; base += 32) {
        int idx = base + lane;
        int c = (idx < end) ? g_ecol[idx] : 0;
        float e = (idx < end) ? a_r + g_aneigh[c] : 0.0f;
        int cnt = min(32, end - base);
        int j = 0;
        for (; j + 4 <= cnt; j += 4) {
#pragma unroll
            for (int u = 0; u < 4; u++) {
                int   cj = __shfl_sync(FULL, c, j + u);
                float ej = __shfl_sync(FULL, e, j + u);
                const float4 h = ((const float4*)(g_h1 + (size_t)cj * 128))[lane];
                acc.x = fmaf(ej, h.x, acc.x);
                acc.y = fmaf(ej, h.y, acc.y);
                acc.z = fmaf(ej, h.z, acc.z);
                acc.w = fmaf(ej, h.w, acc.w);
            }
        }
        for (; j < cnt; j++) {
            int   cj = __shfl_sync(FULL, c, j);
            float ej = __shfl_sync(FULL, e, j);
            const float4 h = ((const float4*)(g_h1 + (size_t)cj * 128))[lane];
            acc.x = fmaf(ej, h.x, acc.x);
            acc.y = fmaf(ej, h.y, acc.y);
            acc.z = fmaf(ej, h.z, acc.z);
            acc.w = fmaf(ej, h.w, acc.w);
        }
    }

    const float4 h0v = ((const float4*)(g_h0 + (size_t)gw * 128))[lane];

    float s0 = h0v.x + h0v.y + h0v.z + h0v.w;
    float q0 = h0v.x * h0v.x + h0v.y * h0v.y + h0v.z * h0v.z + h0v.w * h0v.w;
    float s1 = acc.x + acc.y + acc.z + acc.w;
    float q1 = acc.x * acc.x + acc.y * acc.y + acc.z * acc.z + acc.w * acc.w;

#pragma unroll
    for (int o = 16; o > 0; o >>= 1) {
        s0 += __shfl_xor_sync(FULL, s0, o);
        q0 += __shfl_xor_sync(FULL, q0, o);
        s1 += __shfl_xor_sync(FULL, s1, o);
        q1 += __shfl_xor_sync(FULL, q1, o);
    }

    const float m0 = s0 * (1.0f / 128.0f);
    const float i0 = rsqrtf(q0 * (1.0f / 128.0f) - m0 * m0 + 1e-9f);
    const float m1 = s1 * (1.0f / 128.0f);
    const float i1 = rsqrtf(q1 * (1.0f / 128.0f) - m1 * m1 + 1e-9f);

    const float4 sc0 = ((const float4*)scale0)[lane];
    const float4 of0 = ((const float4*)offset0)[lane];
    const float4 sc1 = ((const float4*)scale1)[lane];
    const float4 of1 = ((const float4*)offset1)[lane];

    float4 o4;
    o4.x = (h0v.x - m0) * sc0.x * i0 + of0.x + (acc.x - m1) * sc1.x * i1 + of1.x;
    o4.y = (h0v.y - m0) * sc0.y * i0 + of0.y + (acc.y - m1) * sc1.y * i1 + of1.y;
    o4.z = (h0v.z - m0) * sc0.z * i0 + of0.z + (acc.z - m1) * sc1.z * i1 + of1.z;
    o4.w = (h0v.w - m0) * sc0.w * i0 + of0.w + (acc.w - m1) * sc1.w * i1 + of1.w;
    ((float4*)(out + (size_t)gw * 128))[lane] = o4;
}

// ---------------------------------------------------------------------------
extern "C" void kernel_launch(void* const* d_in, const int* in_sizes, int n_in,
                              void* d_out, int out_size)
{
    const float* x       = (const float*)d_in[0];
    const int*   row     = (const int*)  d_in[1];
    const int*   col     = (const int*)  d_in[2];
    const float* W0      = (const float*)d_in[3];
    const float* b0      = (const float*)d_in[4];
    const float* W1      = (const float*)d_in[5];
    const float* b1      = (const float*)d_in[6];
    const float* att     = (const float*)d_in[7];
    const float* scale0  = (const float*)d_in[8];
    const float* offset0 = (const float*)d_in[9];
    const float* scale1  = (const float*)d_in[10];
    const float* offset1 = (const float*)d_in[11];
    float* out = (float*)d_out;

    const int N = in_sizes[0] / D;
    const int E = in_sizes[1];
    const int nb = (N + 511) / 512;

    cudaFuncSetAttribute(gemm_kernel, cudaFuncAttributeMaxDynamicSharedMemorySize,
                         GEMM_SMEM);

    dim3 ggrid((N + 127) / 128, 2);
    gemm_kernel<<<ggrid, 256, GEMM_SMEM>>>(x, W0, b0, W1, b1, att, N);
    hist_kernel<<<(E + 255) / 256, 256>>>(row, E);
    scan1_kernel<<<nb, 512>>>(N);
    scan2_kernel<<<1, 512>>>(nb);
    scan3_kernel<<<nb, 512>>>(N);
    scatter_kernel<<<(E + 255) / 256, 256>>>(row, col, E);
    agg_kernel<<<(N * 32 + 255) / 256, 256>>>(scale0, offset0, scale1, offset1, out, N);
}

// round 5
// speedup vs baseline: 2.3917x; 1.1040x over previous
#include <cuda_runtime.h>
#include <cuda_fp16.h>
#include <cstdint>

#define D 128
#define NMAX 100000
#define EMAX 3200000
#define FULL 0xffffffffu

// Scratch in device globals (no runtime allocation).
__device__ float  g_h0[NMAX * D];
__device__ __half g_h1h[NMAX * D];      // h1 in fp16 (agg gather payload)
__device__ float  g_aself[NMAX];
__device__ float  g_aneigh[NMAX];
__device__ int    g_deg[NMAX];
__device__ int    g_off[NMAX + 1];
__device__ int    g_cur[NMAX];
__device__ int2   g_epack[EMAX];        // {col, f32 bits of a_neigh[col]}
__device__ int    g_bsum[512];
__device__ int    g_boff[512];

// ---------------------------------------------------------------------------
// Tensor-core GEMM (tf32 mma.sync m16n8k8).
// Grid (ceil(N/128), 2): cb=0 -> h0 (fp32) + a_self; cb=1 -> h1 (fp16) + a_neigh.
// CTA: 256 thr (8 warps, 4x2), tile 128 rows x 128 cols.
// ---------------------------------------------------------------------------
#define TSTRIDE 132
#define TILE_WORDS (128 * TSTRIDE)
#define GEMM_SMEM ((2 * TILE_WORDS + 3 * 128) * 4)

__device__ __forceinline__ uint32_t f2tf32(float f)
{
    uint32_t u;
    asm("cvt.rna.tf32.f32 %0, %1;" : "=r"(u) : "f"(f));
    return u;
}

__device__ __forceinline__ void mma_tf32(float* c, const uint32_t* a,
                                         uint32_t b0, uint32_t b1)
{
    asm volatile(
        "mma.sync.aligned.m16n8k8.row.col.f32.tf32.tf32.f32 "
        "{%0,%1,%2,%3}, {%4,%5,%6,%7}, {%8,%9}, {%0,%1,%2,%3};"
        : "+f"(c[0]), "+f"(c[1]), "+f"(c[2]), "+f"(c[3])
        : "r"(a[0]), "r"(a[1]), "r"(a[2]), "r"(a[3]), "r"(b0), "r"(b1));
}

__global__ __launch_bounds__(256) void gemm_kernel(
    const float* __restrict__ x,
    const float* __restrict__ W0, const float* __restrict__ b0,
    const float* __restrict__ W1, const float* __restrict__ b1,
    const float* __restrict__ att, int N)
{
    extern __shared__ uint32_t sm[];
    uint32_t* xs = sm;                    // [r][k] tf32 bits, stride 132
    uint32_t* ws = sm + TILE_WORDS;       // [n][k] tf32 bits, stride 132
    float* rowsum = (float*)(sm + 2 * TILE_WORDS);
    float* sbias  = rowsum + 128;
    float* satt   = sbias + 128;

    const int tid  = threadIdx.x;
    const int row0 = blockIdx.x * 128;
    const int cb   = blockIdx.y;
    const float* W  = cb ? W1 : W0;
    const float* bv = cb ? b1 : b0;

    if (tid < 128) {
        rowsum[tid] = 0.0f;
        sbias[tid]  = bv[tid];
        satt[tid]   = att[cb * 128 + tid];
        if (cb == 0 && row0 + tid < N) g_deg[row0 + tid] = 0;
    }

    for (int i = tid; i < 128 * 128; i += 256) {
        int r = i >> 7, c = i & 127;
        int gr = row0 + r;
        float xv = (gr < N) ? x[(size_t)gr * 128 + c] : 0.0f;
        xs[r * TSTRIDE + c] = f2tf32(xv);
        ws[r * TSTRIDE + c] = f2tf32(W[r * 128 + c]);
    }
    __syncthreads();

    const int lane = tid & 31, wid = tid >> 5;
    const int gid  = lane >> 2, tg = lane & 3;
    const int mrow = (wid >> 1) * 32;   // 0,32,64,96
    const int ncol = (wid & 1) * 64;    // 0,64

    float acc[2][8][4];
#pragma unroll
    for (int mt = 0; mt < 2; mt++)
#pragma unroll
        for (int nt = 0; nt < 8; nt++)
#pragma unroll
            for (int q = 0; q < 4; q++) acc[mt][nt][q] = 0.0f;

#pragma unroll 2
    for (int ks = 0; ks < 16; ks++) {
        const int k0 = ks * 8;
        uint32_t a[2][4];
#pragma unroll
        for (int mt = 0; mt < 2; mt++) {
            int r = mrow + mt * 16 + gid;
            a[mt][0] = xs[(r    ) * TSTRIDE + k0 + tg    ];
            a[mt][1] = xs[(r + 8) * TSTRIDE + k0 + tg    ];
            a[mt][2] = xs[(r    ) * TSTRIDE + k0 + tg + 4];
            a[mt][3] = xs[(r + 8) * TSTRIDE + k0 + tg + 4];
        }
#pragma unroll
        for (int nt = 0; nt < 8; nt++) {
            int n = ncol + nt * 8 + gid;
            uint32_t bq0 = ws[n * TSTRIDE + k0 + tg    ];
            uint32_t bq1 = ws[n * TSTRIDE + k0 + tg + 4];
#pragma unroll
            for (int mt = 0; mt < 2; mt++)
                mma_tf32(acc[mt][nt], a[mt], bq0, bq1);
        }
    }

    // Epilogue: bias + relu, store h (fp32 h0 / fp16 h1), attention dot per row.
    float pr[2][2] = {{0.f, 0.f}, {0.f, 0.f}};
#pragma unroll
    for (int mt = 0; mt < 2; mt++) {
        int rbase = row0 + mrow + mt * 16;
#pragma unroll
        for (int nt = 0; nt < 8; nt++) {
            int n = ncol + nt * 8 + 2 * tg;
            float bia0 = sbias[n], bia1 = sbias[n + 1];
            float at0  = satt[n],  at1  = satt[n + 1];
            float v00 = fmaxf(acc[mt][nt][0] + bia0, 0.0f);
            float v01 = fmaxf(acc[mt][nt][1] + bia1, 0.0f);
            float v10 = fmaxf(acc[mt][nt][2] + bia0, 0.0f);
            float v11 = fmaxf(acc[mt][nt][3] + bia1, 0.0f);
            int r0r = rbase + gid, r1r = rbase + gid + 8;
            if (cb == 0) {
                if (r0r < N) *(float2*)(g_h0 + (size_t)r0r * 128 + n) = make_float2(v00, v01);
                if (r1r < N) *(float2*)(g_h0 + (size_t)r1r * 128 + n) = make_float2(v10, v11);
            } else {
                if (r0r < N) *(__half2*)(g_h1h + (size_t)r0r * 128 + n) =
                    __floats2half2_rn(v00, v01);
                if (r1r < N) *(__half2*)(g_h1h + (size_t)r1r * 128 + n) =
                    __floats2half2_rn(v10, v11);
            }
            pr[mt][0] += v00 * at0 + v01 * at1;
            pr[mt][1] += v10 * at0 + v11 * at1;
        }
    }
#pragma unroll
    for (int mt = 0; mt < 2; mt++)
#pragma unroll
        for (int h = 0; h < 2; h++) {
            float p = pr[mt][h];
            p += __shfl_xor_sync(FULL, p, 1);
            p += __shfl_xor_sync(FULL, p, 2);
            pr[mt][h] = p;
        }
    if (tg == 0) {
        atomicAdd(&rowsum[mrow + gid     ], pr[0][0]);
        atomicAdd(&rowsum[mrow + gid + 8 ], pr[0][1]);
        atomicAdd(&rowsum[mrow + gid + 16], pr[1][0]);
        atomicAdd(&rowsum[mrow + gid + 24], pr[1][1]);
    }
    __syncthreads();
    if (tid < 128) {
        int gr = row0 + tid;
        if (gr < N) {
            float p = rowsum[tid];
            p = (p > 0.0f) ? p : 0.2f * p;
            if (cb) g_aneigh[gr] = p;
            else    g_aself[gr]  = p;
        }
    }
}

// ---------------------------------------------------------------------------
// CSR build: histogram -> 3-kernel scan -> cursor scatter (packs e-values)
// ---------------------------------------------------------------------------
__global__ __launch_bounds__(256) void hist_kernel(const int* __restrict__ row, int E)
{
    int i = blockIdx.x * 256 + threadIdx.x;
    if (i < E) atomicAdd(&g_deg[row[i]], 1);
}

__global__ __launch_bounds__(512) void scan1_kernel(int N)
{
    int t = threadIdx.x, b = blockIdx.x;
    int i = b * 512 + t;
    int lane = t & 31, w = t >> 5;
    int v = (i < N) ? g_deg[i] : 0;
#pragma unroll
    for (int o = 1; o < 32; o <<= 1) {
        int n = __shfl_up_sync(FULL, v, o);
        if (lane >= o) v += n;
    }
    __shared__ int ws[16];
    if (lane == 31) ws[w] = v;
    __syncthreads();
    if (w == 0) {
        int s = (lane < 16) ? ws[lane] : 0;
#pragma unroll
        for (int o = 1; o < 16; o <<= 1) {
            int n = __shfl_up_sync(FULL, s, o);
            if (lane >= o) s += n;
        }
        if (lane < 16) ws[lane] = s;
    }
    __syncthreads();
    if (w > 0) v += ws[w - 1];
    if (i < N) g_off[i + 1] = v;
    if (t == 511) g_bsum[b] = v;
}

__global__ __launch_bounds__(512) void scan2_kernel(int nb)
{
    int t = threadIdx.x;
    int lane = t & 31, w = t >> 5;
    int orig = (t < nb) ? g_bsum[t] : 0;
    int v = orig;
#pragma unroll
    for (int o = 1; o < 32; o <<= 1) {
        int n = __shfl_up_sync(FULL, v, o);
        if (lane >= o) v += n;
    }
    __shared__ int ws[16];
    if (lane == 31) ws[w] = v;
    __syncthreads();
    if (w == 0) {
        int s = (lane < 16) ? ws[lane] : 0;
#pragma unroll
        for (int o = 1; o < 16; o <<= 1) {
            int n = __shfl_up_sync(FULL, s, o);
            if (lane >= o) s += n;
        }
        if (lane < 16) ws[lane] = s;
    }
    __syncthreads();
    if (w > 0) v += ws[w - 1];
    if (t < nb) g_boff[t] = v - orig;   // exclusive
}

__global__ __launch_bounds__(512) void scan3_kernel(int N)
{
    int t = threadIdx.x, b = blockIdx.x;
    int i = b * 512 + t;
    if (i < N) {
        int val = g_off[i + 1] + g_boff[b];
        g_off[i + 1] = val;
        g_cur[i] = val - g_deg[i];
    }
    if (i == 0) g_off[0] = 0;
}

__global__ __launch_bounds__(256) void scatter_kernel(
    const int* __restrict__ row, const int* __restrict__ col, int E)
{
    int i = blockIdx.x * 256 + threadIdx.x;
    if (i < E) {
        int c = col[i];
        int pos = atomicAdd(&g_cur[row[i]], 1);
        g_epack[pos] = make_int2(c, __float_as_int(g_aneigh[c]));
    }
}

// ---------------------------------------------------------------------------
// Aggregate + fused epilogue: one warp per node (gather, no atomics).
//   agg = sum_{(r,c)} (a_self[r]+a_neigh[c]) * h1[c]   (h1 fp16, e pre-packed)
//   out[r] = norm(h0[r],s0,o0) + norm(agg,s1,o1)
// ---------------------------------------------------------------------------
__global__ __launch_bounds__(256) void agg_kernel(
    const float* __restrict__ scale0, const float* __restrict__ offset0,
    const float* __restrict__ scale1, const float* __restrict__ offset1,
    float* __restrict__ out, int N)
{
    int gw = (blockIdx.x * blockDim.x + threadIdx.x) >> 5;
    int lane = threadIdx.x & 31;
    if (gw >= N) return;

    const int start = g_off[gw];
    const int end   = g_off[gw + 1];
    const float a_r = g_aself[gw];

    float4 acc = make_float4(0.f, 0.f, 0.f, 0.f);

    for (int base = start; base < end; base += 32) {
        int idx = base + lane;
        int2 p = (idx < end) ? g_epack[idx] : make_int2(0, 0);
        int   c = p.x;
        float e = a_r + __int_as_float(p.y);
        int cnt = min(32, end - base);
        int j = 0;
        for (; j + 4 <= cnt; j += 4) {
#pragma unroll
            for (int u = 0; u < 4; u++) {
                int   cj = __shfl_sync(FULL, c, j + u);
                float ej = __shfl_sync(FULL, e, j + u);
                uint2 hp = ((const uint2*)(g_h1h + (size_t)cj * 128))[lane];
                float2 lo = __half22float2(*(__half2*)&hp.x);
                float2 hi = __half22float2(*(__half2*)&hp.y);
                acc.x = fmaf(ej, lo.x, acc.x);
                acc.y = fmaf(ej, lo.y, acc.y);
                acc.z = fmaf(ej, hi.x, acc.z);
                acc.w = fmaf(ej, hi.y, acc.w);
            }
        }
        for (; j < cnt; j++) {
            int   cj = __shfl_sync(FULL, c, j);
            float ej = __shfl_sync(FULL, e, j);
            uint2 hp = ((const uint2*)(g_h1h + (size_t)cj * 128))[lane];
            float2 lo = __half22float2(*(__half2*)&hp.x);
            float2 hi = __half22float2(*(__half2*)&hp.y);
            acc.x = fmaf(ej, lo.x, acc.x);
            acc.y = fmaf(ej, lo.y, acc.y);
            acc.z = fmaf(ej, hi.x, acc.z);
            acc.w = fmaf(ej, hi.y, acc.w);
        }
    }

    const float4 h0v = ((const float4*)(g_h0 + (size_t)gw * 128))[lane];

    float s0 = h0v.x + h0v.y + h0v.z + h0v.w;
    float q0 = h0v.x * h0v.x + h0v.y * h0v.y + h0v.z * h0v.z + h0v.w * h0v.w;
    float s1 = acc.x + acc.y + acc.z + acc.w;
    float q1 = acc.x * acc.x + acc.y * acc.y + acc.z * acc.z + acc.w * acc.w;

#pragma unroll
    for (int o = 16; o > 0; o >>= 1) {
        s0 += __shfl_xor_sync(FULL, s0, o);
        q0 += __shfl_xor_sync(FULL, q0, o);
        s1 += __shfl_xor_sync(FULL, s1, o);
        q1 += __shfl_xor_sync(FULL, q1, o);
    }

    const float m0 = s0 * (1.0f / 128.0f);
    const float i0 = rsqrtf(q0 * (1.0f / 128.0f) - m0 * m0 + 1e-9f);
    const float m1 = s1 * (1.0f / 128.0f);
    const float i1 = rsqrtf(q1 * (1.0f / 128.0f) - m1 * m1 + 1e-9f);

    const float4 sc0 = ((const float4*)scale0)[lane];
    const float4 of0 = ((const float4*)offset0)[lane];
    const float4 sc1 = ((const float4*)scale1)[lane];
    const float4 of1 = ((const float4*)offset1)[lane];

    float4 o4;
    o4.x = (h0v.x - m0) * sc0.x * i0 + of0.x + (acc.x - m1) * sc1.x * i1 + of1.x;
    o4.y = (h0v.y - m0) * sc0.y * i0 + of0.y + (acc.y - m1) * sc1.y * i1 + of1.y;
    o4.z = (h0v.z - m0) * sc0.z * i0 + of0.z + (acc.z - m1) * sc1.z * i1 + of1.z;
    o4.w = (h0v.w - m0) * sc0.w * i0 + of0.w + (acc.w - m1) * sc1.w * i1 + of1.w;
    ((float4*)(out + (size_t)gw * 128))[lane] = o4;
}

// ---------------------------------------------------------------------------
extern "C" void kernel_launch(void* const* d_in, const int* in_sizes, int n_in,
                              void* d_out, int out_size)
{
    const float* x       = (const float*)d_in[0];
    const int*   row     = (const int*)  d_in[1];
    const int*   col     = (const int*)  d_in[2];
    const float* W0      = (const float*)d_in[3];
    const float* b0      = (const float*)d_in[4];
    const float* W1      = (const float*)d_in[5];
    const float* b1      = (const float*)d_in[6];
    const float* att     = (const float*)d_in[7];
    const float* scale0  = (const float*)d_in[8];
    const float* offset0 = (const float*)d_in[9];
    const float* scale1  = (const float*)d_in[10];
    const float* offset1 = (const float*)d_in[11];
    float* out = (float*)d_out;

    const int N = in_sizes[0] / D;
    const int E = in_sizes[1];
    const int nb = (N + 511) / 512;

    cudaFuncSetAttribute(gemm_kernel, cudaFuncAttributeMaxDynamicSharedMemorySize,
                         GEMM_SMEM);

    dim3 ggrid((N + 127) / 128, 2);
    gemm_kernel<<<ggrid, 256, GEMM_SMEM>>>(x, W0, b0, W1, b1, att, N);
    hist_kernel<<<(E + 255) / 256, 256>>>(row, E);
    scan1_kernel<<<nb, 512>>>(N);
    scan2_kernel<<<1, 512>>>(nb);
    scan3_kernel<<<nb, 512>>>(N);
    scatter_kernel<<<(E + 255) / 256, 256>>>(row, col, E);
    agg_kernel<<<(N * 32 + 255) / 256, 256>>>(scale0, offset0, scale1, offset1, out, N);
}

// round 6
// speedup vs baseline: 2.4039x; 1.0051x over previous
#include <cuda_runtime.h>
#include <cuda_fp16.h>
#include <cstdint>

#define D 128
#define NMAX 100000
#define EMAX 3200000
#define FULL 0xffffffffu

// Scratch in device globals (no runtime allocation).
__device__ float  g_h0[NMAX * D];
__device__ __half g_h1h[NMAX * D];      // h1 in fp16 (agg gather payload)
__device__ float  g_aself[NMAX];
__device__ float  g_aneigh[NMAX];
__device__ int    g_deg[NMAX];
__device__ int    g_off[NMAX + 1];
__device__ int    g_cur[NMAX];
__device__ int2   g_epack[EMAX];        // {col, f32 bits of a_neigh[col]}
__device__ int    g_bsum[512];
__device__ int    g_boff[512];

// ---------------------------------------------------------------------------
// Tensor-core GEMM (tf32 mma.sync m16n8k8).
// Grid (ceil(N/128), 2): cb=0 -> h0 (fp32) + a_self; cb=1 -> h1 (fp16) + a_neigh.
// CTA: 256 thr (8 warps, 4x2), tile 128 rows x 128 cols.
// ---------------------------------------------------------------------------
#define TSTRIDE 132
#define TILE_WORDS (128 * TSTRIDE)
#define GEMM_SMEM ((2 * TILE_WORDS + 3 * 128) * 4)

__device__ __forceinline__ uint32_t f2tf32(float f)
{
    uint32_t u;
    asm("cvt.rna.tf32.f32 %0, %1;" : "=r"(u) : "f"(f));
    return u;
}

__device__ __forceinline__ void mma_tf32(float* c, const uint32_t* a,
                                         uint32_t b0, uint32_t b1)
{
    asm volatile(
        "mma.sync.aligned.m16n8k8.row.col.f32.tf32.tf32.f32 "
        "{%0,%1,%2,%3}, {%4,%5,%6,%7}, {%8,%9}, {%0,%1,%2,%3};"
        : "+f"(c[0]), "+f"(c[1]), "+f"(c[2]), "+f"(c[3])
        : "r"(a[0]), "r"(a[1]), "r"(a[2]), "r"(a[3]), "r"(b0), "r"(b1));
}

__global__ __launch_bounds__(256) void gemm_kernel(
    const float* __restrict__ x,
    const float* __restrict__ W0, const float* __restrict__ b0,
    const float* __restrict__ W1, const float* __restrict__ b1,
    const float* __restrict__ att, int N)
{
    extern __shared__ uint32_t sm[];
    uint32_t* xs = sm;                    // [r][k] tf32 bits, stride 132
    uint32_t* ws = sm + TILE_WORDS;       // [n][k] tf32 bits, stride 132
    float* rowsum = (float*)(sm + 2 * TILE_WORDS);
    float* sbias  = rowsum + 128;
    float* satt   = sbias + 128;

    const int tid  = threadIdx.x;
    const int row0 = blockIdx.x * 128;
    const int cb   = blockIdx.y;
    const float* W  = cb ? W1 : W0;
    const float* bv = cb ? b1 : b0;

    if (tid < 128) {
        rowsum[tid] = 0.0f;
        sbias[tid]  = bv[tid];
        satt[tid]   = att[cb * 128 + tid];
        if (cb == 0 && row0 + tid < N) g_deg[row0 + tid] = 0;
    }

    for (int i = tid; i < 128 * 128; i += 256) {
        int r = i >> 7, c = i & 127;
        int gr = row0 + r;
        float xv = (gr < N) ? x[(size_t)gr * 128 + c] : 0.0f;
        xs[r * TSTRIDE + c] = f2tf32(xv);
        ws[r * TSTRIDE + c] = f2tf32(W[r * 128 + c]);
    }
    __syncthreads();

    const int lane = tid & 31, wid = tid >> 5;
    const int gid  = lane >> 2, tg = lane & 3;
    const int mrow = (wid >> 1) * 32;   // 0,32,64,96
    const int ncol = (wid & 1) * 64;    // 0,64

    float acc[2][8][4];
#pragma unroll
    for (int mt = 0; mt < 2; mt++)
#pragma unroll
        for (int nt = 0; nt < 8; nt++)
#pragma unroll
            for (int q = 0; q < 4; q++) acc[mt][nt][q] = 0.0f;

#pragma unroll 2
    for (int ks = 0; ks < 16; ks++) {
        const int k0 = ks * 8;
        uint32_t a[2][4];
#pragma unroll
        for (int mt = 0; mt < 2; mt++) {
            int r = mrow + mt * 16 + gid;
            a[mt][0] = xs[(r    ) * TSTRIDE + k0 + tg    ];
            a[mt][1] = xs[(r + 8) * TSTRIDE + k0 + tg    ];
            a[mt][2] = xs[(r    ) * TSTRIDE + k0 + tg + 4];
            a[mt][3] = xs[(r + 8) * TSTRIDE + k0 + tg + 4];
        }
#pragma unroll
        for (int nt = 0; nt < 8; nt++) {
            int n = ncol + nt * 8 + gid;
            uint32_t bq0 = ws[n * TSTRIDE + k0 + tg    ];
            uint32_t bq1 = ws[n * TSTRIDE + k0 + tg + 4];
#pragma unroll
            for (int mt = 0; mt < 2; mt++)
                mma_tf32(acc[mt][nt], a[mt], bq0, bq1);
        }
    }

    // Epilogue: bias + relu, store h (fp32 h0 / fp16 h1), attention dot per row.
    float pr[2][2] = {{0.f, 0.f}, {0.f, 0.f}};
#pragma unroll
    for (int mt = 0; mt < 2; mt++) {
        int rbase = row0 + mrow + mt * 16;
#pragma unroll
        for (int nt = 0; nt < 8; nt++) {
            int n = ncol + nt * 8 + 2 * tg;
            float bia0 = sbias[n], bia1 = sbias[n + 1];
            float at0  = satt[n],  at1  = satt[n + 1];
            float v00 = fmaxf(acc[mt][nt][0] + bia0, 0.0f);
            float v01 = fmaxf(acc[mt][nt][1] + bia1, 0.0f);
            float v10 = fmaxf(acc[mt][nt][2] + bia0, 0.0f);
            float v11 = fmaxf(acc[mt][nt][3] + bia1, 0.0f);
            int r0r = rbase + gid, r1r = rbase + gid + 8;
            if (cb == 0) {
                if (r0r < N) *(float2*)(g_h0 + (size_t)r0r * 128 + n) = make_float2(v00, v01);
                if (r1r < N) *(float2*)(g_h0 + (size_t)r1r * 128 + n) = make_float2(v10, v11);
            } else {
                if (r0r < N) *(__half2*)(g_h1h + (size_t)r0r * 128 + n) =
                    __floats2half2_rn(v00, v01);
                if (r1r < N) *(__half2*)(g_h1h + (size_t)r1r * 128 + n) =
                    __floats2half2_rn(v10, v11);
            }
            pr[mt][0] += v00 * at0 + v01 * at1;
            pr[mt][1] += v10 * at0 + v11 * at1;
        }
    }
#pragma unroll
    for (int mt = 0; mt < 2; mt++)
#pragma unroll
        for (int h = 0; h < 2; h++) {
            float p = pr[mt][h];
            p += __shfl_xor_sync(FULL, p, 1);
            p += __shfl_xor_sync(FULL, p, 2);
            pr[mt][h] = p;
        }
    if (tg == 0) {
        atomicAdd(&rowsum[mrow + gid     ], pr[0][0]);
        atomicAdd(&rowsum[mrow + gid + 8 ], pr[0][1]);
        atomicAdd(&rowsum[mrow + gid + 16], pr[1][0]);
        atomicAdd(&rowsum[mrow + gid + 24], pr[1][1]);
    }
    __syncthreads();
    if (tid < 128) {
        int gr = row0 + tid;
        if (gr < N) {
            float p = rowsum[tid];
            p = (p > 0.0f) ? p : 0.2f * p;
            if (cb) g_aneigh[gr] = p;
            else    g_aself[gr]  = p;
        }
    }
}

// ---------------------------------------------------------------------------
// CSR build: histogram -> 3-kernel scan -> cursor scatter (packs e-values)
// ---------------------------------------------------------------------------
__global__ __launch_bounds__(256) void hist_kernel(const int* __restrict__ row, int E)
{
    int i = blockIdx.x * 256 + threadIdx.x;
    if (i < E) atomicAdd(&g_deg[row[i]], 1);
}

__global__ __launch_bounds__(512) void scan1_kernel(int N)
{
    int t = threadIdx.x, b = blockIdx.x;
    int i = b * 512 + t;
    int lane = t & 31, w = t >> 5;
    int v = (i < N) ? g_deg[i] : 0;
#pragma unroll
    for (int o = 1; o < 32; o <<= 1) {
        int n = __shfl_up_sync(FULL, v, o);
        if (lane >= o) v += n;
    }
    __shared__ int ws[16];
    if (lane == 31) ws[w] = v;
    __syncthreads();
    if (w == 0) {
        int s = (lane < 16) ? ws[lane] : 0;
#pragma unroll
        for (int o = 1; o < 16; o <<= 1) {
            int n = __shfl_up_sync(FULL, s, o);
            if (lane >= o) s += n;
        }
        if (lane < 16) ws[lane] = s;
    }
    __syncthreads();
    if (w > 0) v += ws[w - 1];
    if (i < N) g_off[i + 1] = v;
    if (t == 511) g_bsum[b] = v;
}

__global__ __launch_bounds__(512) void scan2_kernel(int nb)
{
    int t = threadIdx.x;
    int lane = t & 31, w = t >> 5;
    int orig = (t < nb) ? g_bsum[t] : 0;
    int v = orig;
#pragma unroll
    for (int o = 1; o < 32; o <<= 1) {
        int n = __shfl_up_sync(FULL, v, o);
        if (lane >= o) v += n;
    }
    __shared__ int ws[16];
    if (lane == 31) ws[w] = v;
    __syncthreads();
    if (w == 0) {
        int s = (lane < 16) ? ws[lane] : 0;
#pragma unroll
        for (int o = 1; o < 16; o <<= 1) {
            int n = __shfl_up_sync(FULL, s, o);
            if (lane >= o) s += n;
        }
        if (lane < 16) ws[lane] = s;
    }
    __syncthreads();
    if (w > 0) v += ws[w - 1];
    if (t < nb) g_boff[t] = v - orig;   // exclusive
}

__global__ __launch_bounds__(512) void scan3_kernel(int N)
{
    int t = threadIdx.x, b = blockIdx.x;
    int i = b * 512 + t;
    if (i < N) {
        int val = g_off[i + 1] + g_boff[b];
        g_off[i + 1] = val;
        g_cur[i] = val - g_deg[i];
    }
    if (i == 0) g_off[0] = 0;
}

__global__ __launch_bounds__(256) void scatter_kernel(
    const int* __restrict__ row, const int* __restrict__ col, int E)
{
    int i = blockIdx.x * 256 + threadIdx.x;
    if (i < E) {
        int c = col[i];
        int pos = atomicAdd(&g_cur[row[i]], 1);
        g_epack[pos] = make_int2(c, __float_as_int(g_aneigh[c]));
    }
}

// ---------------------------------------------------------------------------
// Aggregate + fused epilogue: one warp per node (gather, no atomics).
//   agg = sum_{(r,c)} (a_self[r]+a_neigh[c]) * h1[c]   (h1 fp16, e pre-packed)
//   out[r] = norm(h0[r],s0,o0) + norm(agg,s1,o1)
// ---------------------------------------------------------------------------
__global__ __launch_bounds__(256) void agg_kernel(
    const float* __restrict__ scale0, const float* __restrict__ offset0,
    const float* __restrict__ scale1, const float* __restrict__ offset1,
    float* __restrict__ out, int N)
{
    int gw = (blockIdx.x * blockDim.x + threadIdx.x) >> 5;
    int lane = threadIdx.x & 31;
    if (gw >= N) return;

    const int start = g_off[gw];
    const int end   = g_off[gw + 1];
    const float a_r = g_aself[gw];

    float4 acc = make_float4(0.f, 0.f, 0.f, 0.f);

    for (int base = start; base < end; base += 32) {
        int idx = base + lane;
        int2 p = (idx < end) ? g_epack[idx] : make_int2(0, 0);
        int   c = p.x;
        float e = a_r + __int_as_float(p.y);
        int cnt = min(32, end - base);
        int j = 0;
        for (; j + 4 <= cnt; j += 4) {
#pragma unroll
            for (int u = 0; u < 4; u++) {
                int   cj = __shfl_sync(FULL, c, j + u);
                float ej = __shfl_sync(FULL, e, j + u);
                uint2 hp = ((const uint2*)(g_h1h + (size_t)cj * 128))[lane];
                float2 lo = __half22float2(*(__half2*)&hp.x);
                float2 hi = __half22float2(*(__half2*)&hp.y);
                acc.x = fmaf(ej, lo.x, acc.x);
                acc.y = fmaf(ej, lo.y, acc.y);
                acc.z = fmaf(ej, hi.x, acc.z);
                acc.w = fmaf(ej, hi.y, acc.w);
            }
        }
        for (; j < cnt; j++) {
            int   cj = __shfl_sync(FULL, c, j);
            float ej = __shfl_sync(FULL, e, j);
            uint2 hp = ((const uint2*)(g_h1h + (size_t)cj * 128))[lane];
            float2 lo = __half22float2(*(__half2*)&hp.x);
            float2 hi = __half22float2(*(__half2*)&hp.y);
            acc.x = fmaf(ej, lo.x, acc.x);
            acc.y = fmaf(ej, lo.y, acc.y);
            acc.z = fmaf(ej, hi.x, acc.z);
            acc.w = fmaf(ej, hi.y, acc.w);
        }
    }

    const float4 h0v = ((const float4*)(g_h0 + (size_t)gw * 128))[lane];

    float s0 = h0v.x + h0v.y + h0v.z + h0v.w;
    float q0 = h0v.x * h0v.x + h0v.y * h0v.y + h0v.z * h0v.z + h0v.w * h0v.w;
    float s1 = acc.x + acc.y + acc.z + acc.w;
    float q1 = acc.x * acc.x + acc.y * acc.y + acc.z * acc.z + acc.w * acc.w;

#pragma unroll
    for (int o = 16; o > 0; o >>= 1) {
        s0 += __shfl_xor_sync(FULL, s0, o);
        q0 += __shfl_xor_sync(FULL, q0, o);
        s1 += __shfl_xor_sync(FULL, s1, o);
        q1 += __shfl_xor_sync(FULL, q1, o);
    }

    const float m0 = s0 * (1.0f / 128.0f);
    const float i0 = rsqrtf(q0 * (1.0f / 128.0f) - m0 * m0 + 1e-9f);
    const float m1 = s1 * (1.0f / 128.0f);
    const float i1 = rsqrtf(q1 * (1.0f / 128.0f) - m1 * m1 + 1e-9f);

    const float4 sc0 = ((const float4*)scale0)[lane];
    const float4 of0 = ((const float4*)offset0)[lane];
    const float4 sc1 = ((const float4*)scale1)[lane];
    const float4 of1 = ((const float4*)offset1)[lane];

    float4 o4;
    o4.x = (h0v.x - m0) * sc0.x * i0 + of0.x + (acc.x - m1) * sc1.x * i1 + of1.x;
    o4.y = (h0v.y - m0) * sc0.y * i0 + of0.y + (acc.y - m1) * sc1.y * i1 + of1.y;
    o4.z = (h0v.z - m0) * sc0.z * i0 + of0.z + (acc.z - m1) * sc1.z * i1 + of1.z;
    o4.w = (h0v.w - m0) * sc0.w * i0 + of0.w + (acc.w - m1) * sc1.w * i1 + of1.w;
    ((float4*)(out + (size_t)gw * 128))[lane] = o4;
}

// ---------------------------------------------------------------------------
extern "C" void kernel_launch(void* const* d_in, const int* in_sizes, int n_in,
                              void* d_out, int out_size)
{
    const float* x       = (const float*)d_in[0];
    const int*   row     = (const int*)  d_in[1];
    const int*   col     = (const int*)  d_in[2];
    const float* W0      = (const float*)d_in[3];
    const float* b0      = (const float*)d_in[4];
    const float* W1      = (const float*)d_in[5];
    const float* b1      = (const float*)d_in[6];
    const float* att     = (const float*)d_in[7];
    const float* scale0  = (const float*)d_in[8];
    const float* offset0 = (const float*)d_in[9];
    const float* scale1  = (const float*)d_in[10];
    const float* offset1 = (const float*)d_in[11];
    float* out = (float*)d_out;

    const int N = in_sizes[0] / D;
    const int E = in_sizes[1];
    const int nb = (N + 511) / 512;

    cudaFuncSetAttribute(gemm_kernel, cudaFuncAttributeMaxDynamicSharedMemorySize,
                         GEMM_SMEM);

    dim3 ggrid((N + 127) / 128, 2);
    gemm_kernel<<<ggrid, 256, GEMM_SMEM>>>(x, W0, b0, W1, b1, att, N);
    hist_kernel<<<(E + 255) / 256, 256>>>(row, E);
    scan1_kernel<<<nb, 512>>>(N);
    scan2_kernel<<<1, 512>>>(nb);
    scan3_kernel<<<nb, 512>>>(N);
    scatter_kernel<<<(E + 255) / 256, 256>>>(row, col, E);
    agg_kernel<<<(N * 32 + 255) / 256, 256>>>(scale0, offset0, scale1, offset1, out, N);
}